// round 15
// baseline (speedup 1.0000x reference)
#include <cuda_runtime.h>
#include <cuda_fp16.h>
#include <cstdint>

#define NN 50000
#define NE 800000
#define DIM 128
#define NO 384   /* 3*HIDDEN */

// ---------------- scratch (device globals: allocation-free) ----------------
// NOTE: g_degout/g_degin are zero at module load (.bss) and re-zeroed at the END
// of every kernel_launch (in gru_kernel), so deg_kernel always sees zeros.
__device__ __half g_fh16[(size_t)NN * 256];  // [node][0:128)=nsrc*feat, [128:256)=nsrc*hx
__device__ __half g_a16f[(size_t)NN * DIM];  // fp16 A matrices (ndst folded)
__device__ __half g_a16h[(size_t)NN * DIM];
__device__ __half g_C1[(size_t)NN * NO];     // fp16 intermediates
__device__ __half g_C2[(size_t)NN * NO];
__device__ __half g_Bih[NO * DIM];   // Wi^T fp16  [n][k]
__device__ __half g_Bhh[NO * DIM];   // Wh^T fp16
__device__ float g_nsrc[NN];
__device__ float g_ndst[NN];
__device__ int   g_degout[NN];
__device__ int   g_degin[NN];
__device__ int   g_off[NN + 1];
__device__ int   g_cur[NN];
__device__ int   g_csrc[NE];

__device__ __forceinline__ uint32_t smem_u32(const void* p) {
    uint32_t a;
    asm("{ .reg .u64 t; cvta.to.shared.u64 t, %1; cvt.u32.u64 %0, t; }" : "=r"(a) : "l"(p));
    return a;
}

// ---------------- kernel 1: degrees (counters pre-zeroed by previous launch) ------
__global__ void deg_kernel(const int* __restrict__ src, const int* __restrict__ dst) {
    int e = blockIdx.x * blockDim.x + threadIdx.x;
    if (e < NE) {
        atomicAdd(&g_degout[src[e]], 1);
        atomicAdd(&g_degin[dst[e]], 1);
    }
}

// ---------------- kernel 2: exclusive scan of degin + norms (single block) --------
__global__ __launch_bounds__(1024) void scan_kernel() {
    __shared__ int sm[1024];
    int t = threadIdx.x;
    const int CH = 49;                       // 1024*49 = 50176 >= NN
    int base = t * CH;
    int s = 0;
#pragma unroll
    for (int i = 0; i < CH; i++) {
        int idx = base + i;
        s += (idx < NN) ? g_degin[idx] : 0;
    }
    sm[t] = s;
    __syncthreads();
    for (int d = 1; d < 1024; d <<= 1) {
        int v = (t >= d) ? sm[t - d] : 0;
        __syncthreads();
        sm[t] += v;
        __syncthreads();
    }
    int run = (t == 0) ? 0 : sm[t - 1];
#pragma unroll
    for (int i = 0; i < CH; i++) {
        int idx = base + i;
        if (idx < NN) {
            g_off[idx] = run;
            g_cur[idx] = run;
            run += g_degin[idx];
        }
    }
    if (t == 1023) g_off[NN] = run;
    for (int i = t; i < NN; i += 1024) {
        g_nsrc[i] = rsqrtf(fmaxf((float)g_degout[i], 1.f));
        g_ndst[i] = rsqrtf(fmaxf((float)g_degin[i], 1.f));
    }
}

// ---------------- kernel 3: merged mid stage (conv + csr + prepw) -----------------
__global__ __launch_bounds__(256) void mid_kernel(
    const float* __restrict__ feat, const float* __restrict__ hx,
    const float* __restrict__ Wi, const float* __restrict__ Wh,
    const int* __restrict__ src, const int* __restrict__ dst)
{
    int i = blockIdx.x * blockDim.x + threadIdx.x;

    // --- conv: feat/hx -> interleaved fp16 with nsrc pre-folded ---
    if (i < NN * DIM / 4) {
        int n = i >> 5, q = i & 31;
        float ns = g_nsrc[n];
        float4 f = reinterpret_cast<const float4*>(feat)[i];
        float4 h = reinterpret_cast<const float4*>(hx)[i];
        __half2 f01 = __float22half2_rn(make_float2(ns * f.x, ns * f.y));
        __half2 f23 = __float22half2_rn(make_float2(ns * f.z, ns * f.w));
        __half2 h01 = __float22half2_rn(make_float2(ns * h.x, ns * h.y));
        __half2 h23 = __float22half2_rn(make_float2(ns * h.z, ns * h.w));
        uint2* fh = reinterpret_cast<uint2*>(g_fh16);
        fh[n * 64 + q] =
            make_uint2(*reinterpret_cast<uint32_t*>(&f01), *reinterpret_cast<uint32_t*>(&f23));
        fh[n * 64 + 32 + q] =
            make_uint2(*reinterpret_cast<uint32_t*>(&h01), *reinterpret_cast<uint32_t*>(&h23));
    }

    // --- csr: bin edges by dst ---
    if (i < NE) {
        int d = dst[i];
        int pos = atomicAdd(&g_cur[d], 1);
        g_csrc[pos] = src[i];
    }

    // --- prepw: W^T -> fp16 ---
    if (i < NO * DIM) {
        int n = i >> 7, k = i & 127;
        g_Bih[i] = __float2half(Wi[k * NO + n]);
        g_Bhh[i] = __float2half(Wh[k * NO + n]);
    }
}

// ---------------- kernel 4: aggregation (warp per dst, 1 LDG.128/edge) ------------
__device__ __forceinline__ void acc8(uint4 v, float4& a0, float4& a1) {
    float2 x = __half22float2(*reinterpret_cast<__half2*>(&v.x));
    float2 y = __half22float2(*reinterpret_cast<__half2*>(&v.y));
    float2 z = __half22float2(*reinterpret_cast<__half2*>(&v.z));
    float2 w = __half22float2(*reinterpret_cast<__half2*>(&v.w));
    a0.x += x.x; a0.y += x.y; a0.z += y.x; a0.w += y.y;
    a1.x += z.x; a1.y += z.y; a1.z += w.x; a1.w += w.y;
}

__global__ __launch_bounds__(256) void agg_kernel() {
    int w = (blockIdx.x * blockDim.x + threadIdx.x) >> 5;
    int lane = threadIdx.x & 31;
    if (w >= NN) return;
    int beg = g_off[w], end = g_off[w + 1];
    const uint4* fh = reinterpret_cast<const uint4*>(g_fh16);
    float4 a0 = make_float4(0.f, 0.f, 0.f, 0.f);
    float4 a1 = make_float4(0.f, 0.f, 0.f, 0.f);
    int p = beg;
    for (; p + 7 < end; p += 8) {
        int s[8];
        uint4 v[8];
#pragma unroll
        for (int j = 0; j < 8; j++) s[j] = __ldg(g_csrc + p + j);
#pragma unroll
        for (int j = 0; j < 8; j++) v[j] = fh[s[j] * 32 + lane];
#pragma unroll
        for (int j = 0; j < 8; j++) acc8(v[j], a0, a1);
    }
    for (; p < end; p++) {
        int s = __ldg(g_csrc + p);
        uint4 v = fh[s * 32 + lane];
        acc8(v, a0, a1);
    }
    float nd = g_ndst[w];
    a0.x *= nd; a0.y *= nd; a0.z *= nd; a0.w *= nd;
    a1.x *= nd; a1.y *= nd; a1.z *= nd; a1.w *= nd;
    __half2 o0 = __float22half2_rn(make_float2(a0.x, a0.y));
    __half2 o1 = __float22half2_rn(make_float2(a0.z, a0.w));
    __half2 o2 = __float22half2_rn(make_float2(a1.x, a1.y));
    __half2 o3 = __float22half2_rn(make_float2(a1.z, a1.w));
    uint4 o = make_uint4(*reinterpret_cast<uint32_t*>(&o0), *reinterpret_cast<uint32_t*>(&o1),
                         *reinterpret_cast<uint32_t*>(&o2), *reinterpret_cast<uint32_t*>(&o3));
    if (lane < 16) reinterpret_cast<uint4*>(g_a16f)[w * 16 + lane] = o;
    else           reinterpret_cast<uint4*>(g_a16h)[w * 16 + lane - 16] = o;
}

// ---------------- kernel 5: mma.sync fp16 GEMM, both operands cp.async ------------
// CTA tile 128(M) x 128(N), occupancy 3, warp tile 64x32 (2x4 warps).
#define PITCH 136                         /* fp16 per smem row (272B) */
#define S_A  0
#define S_B  (128 * PITCH * 2)            /* 34816 */
#define GEMM_SMEM (S_B + 128 * PITCH * 2) /* 69632; x3 CTAs <= 227KB */

__global__ __launch_bounds__(256, 3) void gemm_kernel() {
    extern __shared__ char smem[];
    uint32_t sb = smem_u32(smem);
    int tid = threadIdx.x, lane = tid & 31, wid = tid >> 5;
    int warp_m = wid & 1, warp_n = wid >> 1;   // 2 x 4 warps, warp tile 64 x 32
    int m0 = blockIdx.x * 128, n0 = blockIdx.y * 128;
    const __half* A      = blockIdx.z ? g_a16h : g_a16f;
    const __half* B      = blockIdx.z ? g_Bhh  : g_Bih;
    __half* C            = blockIdx.z ? g_C2   : g_C1;

    // ---- A and B tiles via cp.async (128 rows x 16 uint4 each) ----
    {
        const uint4* AU = reinterpret_cast<const uint4*>(A);
        const uint4* BU = reinterpret_cast<const uint4*>(B);
#pragma unroll
        for (int i = 0; i < 8; i++) {
            int p = tid + i * 256;               // 2048 per tile
            int r = p >> 4, q = p & 15;
            uint32_t doff = (uint32_t)(r * PITCH * 2 + q * 16);
            int gm = m0 + r;
            if (gm < NN) {
                const uint4* ga = AU + gm * 16 + q;
                asm volatile("cp.async.cg.shared.global [%0], [%1], 16;"
                             :: "r"(sb + S_A + doff), "l"(ga) : "memory");
            } else {
                *reinterpret_cast<uint4*>(smem + S_A + doff) = make_uint4(0u, 0u, 0u, 0u);
            }
            const uint4* gb = BU + (n0 + r) * 16 + q;
            asm volatile("cp.async.cg.shared.global [%0], [%1], 16;"
                         :: "r"(sb + S_B + doff), "l"(gb) : "memory");
        }
        asm volatile("cp.async.commit_group;" ::: "memory");
        asm volatile("cp.async.wait_group 0;" ::: "memory");
    }
    __syncthreads();

    float acc[4][4][4];
#pragma unroll
    for (int mi = 0; mi < 4; mi++)
#pragma unroll
        for (int ni = 0; ni < 4; ni++)
#pragma unroll
            for (int j = 0; j < 4; j++) acc[mi][ni][j] = 0.f;

    int a_row = (lane & 7) + ((lane >> 3) & 1) * 8;
    int a_kof = (lane >> 4) * 8;
    int b_row = (lane & 7) + (lane >> 4) * 8;
    int b_kof = ((lane >> 3) & 1) * 8;

    uint32_t sA = sb + S_A;
    uint32_t sB = sb + S_B;
#pragma unroll
    for (int ks = 0; ks < 8; ks++) {
        int k0 = ks * 16;
        uint32_t a[4][4], b[4][2];
#pragma unroll
        for (int mi = 0; mi < 4; mi++) {
            uint32_t addr = sA + ((warp_m * 64 + mi * 16 + a_row) * PITCH + k0 + a_kof) * 2;
            asm volatile("ldmatrix.sync.aligned.m8n8.x4.shared.b16 {%0,%1,%2,%3}, [%4];"
                         : "=r"(a[mi][0]), "=r"(a[mi][1]), "=r"(a[mi][2]), "=r"(a[mi][3])
                         : "r"(addr));
        }
#pragma unroll
        for (int nh = 0; nh < 2; nh++) {
            uint32_t addr = sB + ((warp_n * 32 + nh * 16 + b_row) * PITCH + k0 + b_kof) * 2;
            uint32_t r0, r1, r2, r3;
            asm volatile("ldmatrix.sync.aligned.m8n8.x4.shared.b16 {%0,%1,%2,%3}, [%4];"
                         : "=r"(r0), "=r"(r1), "=r"(r2), "=r"(r3)
                         : "r"(addr));
            b[nh * 2][0] = r0; b[nh * 2][1] = r1;
            b[nh * 2 + 1][0] = r2; b[nh * 2 + 1][1] = r3;
        }
#pragma unroll
        for (int mi = 0; mi < 4; mi++)
#pragma unroll
            for (int ni = 0; ni < 4; ni++) {
                asm volatile(
                    "mma.sync.aligned.m16n8k16.row.col.f32.f16.f16.f32 "
                    "{%0,%1,%2,%3}, {%4,%5,%6,%7}, {%8,%9}, {%0,%1,%2,%3};"
                    : "+f"(acc[mi][ni][0]), "+f"(acc[mi][ni][1]),
                      "+f"(acc[mi][ni][2]), "+f"(acc[mi][ni][3])
                    : "r"(a[mi][0]), "r"(a[mi][1]), "r"(a[mi][2]), "r"(a[mi][3]),
                      "r"(b[ni][0]), "r"(b[ni][1]));
            }
    }

    // ---- epilogue: fp16 stores ----
#pragma unroll
    for (int mi = 0; mi < 4; mi++) {
        int row = m0 + warp_m * 64 + mi * 16 + (lane >> 2);
#pragma unroll
        for (int ni = 0; ni < 4; ni++) {
            int col = n0 + warp_n * 32 + ni * 8 + (lane & 3) * 2;
            if (row < NN) {
                *reinterpret_cast<__half2*>(C + (size_t)row * NO + col) =
                    __float22half2_rn(make_float2(acc[mi][ni][0], acc[mi][ni][1]));
            }
            if (row + 8 < NN) {
                *reinterpret_cast<__half2*>(C + (size_t)(row + 8) * NO + col) =
                    __float22half2_rn(make_float2(acc[mi][ni][2], acc[mi][ni][3]));
            }
        }
    }
}

// ---------------- kernel 6: GRU gating + counter re-zero for next launch ----------
__global__ __launch_bounds__(256) void gru_kernel(
    const float* __restrict__ hx, const float* __restrict__ bi,
    const float* __restrict__ bh, float* __restrict__ out)
{
    int idx = blockIdx.x * blockDim.x + threadIdx.x;   // NN * 64 threads
    if (idx < NN) { g_degout[idx] = 0; g_degin[idx] = 0; }   // prep next launch
    if (idx >= NN * 64) return;
    int n = idx >> 6, ch = (idx & 63);
    const __half2* c1 = reinterpret_cast<const __half2*>(g_C1 + (size_t)n * NO);
    const __half2* c2 = reinterpret_cast<const __half2*>(g_C2 + (size_t)n * NO);
    int c = ch * 2;
    float2 c1r = __half22float2(c1[ch]);
    float2 c1z = __half22float2(c1[ch + 64]);
    float2 c1n = __half22float2(c1[ch + 128]);
    float2 c2r = __half22float2(c2[ch]);
    float2 c2z = __half22float2(c2[ch + 64]);
    float2 c2n = __half22float2(c2[ch + 128]);
    float2 bir = *reinterpret_cast<const float2*>(bi + c);
    float2 biz = *reinterpret_cast<const float2*>(bi + c + 128);
    float2 bin = *reinterpret_cast<const float2*>(bi + c + 256);
    float2 bhr = *reinterpret_cast<const float2*>(bh + c);
    float2 bhz = *reinterpret_cast<const float2*>(bh + c + 128);
    float2 bhn = *reinterpret_cast<const float2*>(bh + c + 256);
    float2 hv = *reinterpret_cast<const float2*>(hx + (size_t)n * DIM + c);
    float2 o;
    {
        float r = 1.f / (1.f + __expf(-(c1r.x + c2r.x + bir.x + bhr.x)));
        float z = 1.f / (1.f + __expf(-(c1z.x + c2z.x + biz.x + bhz.x)));
        float nn = tanhf(c1n.x + bin.x + r * (c2n.x + bhn.x));
        o.x = (1.f - z) * nn + z * hv.x;
    }
    {
        float r = 1.f / (1.f + __expf(-(c1r.y + c2r.y + bir.y + bhr.y)));
        float z = 1.f / (1.f + __expf(-(c1z.y + c2z.y + biz.y + bhz.y)));
        float nn = tanhf(c1n.y + bin.y + r * (c2n.y + bhn.y));
        o.y = (1.f - z) * nn + z * hv.y;
    }
    *reinterpret_cast<float2*>(out + (size_t)n * DIM + c) = o;
}

// ---------------- launch ----------------
extern "C" void kernel_launch(void* const* d_in, const int* in_sizes, int n_in,
                              void* d_out, int out_size)
{
    const float* feat = (const float*)d_in[0];
    const float* hx   = (const float*)d_in[1];
    const float* Wi   = (const float*)d_in[2];
    const float* bi   = (const float*)d_in[3];
    const float* Wh   = (const float*)d_in[4];
    const float* bh   = (const float*)d_in[5];
    const int*   src  = (const int*)d_in[6];
    const int*   dst  = (const int*)d_in[7];
    float* out = (float*)d_out;

    cudaFuncSetAttribute(gemm_kernel, cudaFuncAttributeMaxDynamicSharedMemorySize, GEMM_SMEM);

    deg_kernel<<<(NE + 255) / 256, 256>>>(src, dst);
    scan_kernel<<<1, 1024>>>();
    mid_kernel<<<(NN * DIM / 4 + 255) / 256, 256>>>(feat, hx, Wi, Wh, src, dst);
    agg_kernel<<<(NN * 32 + 255) / 256, 256>>>();
    gemm_kernel<<<dim3((NN + 127) / 128, NO / 128, 2), 256, GEMM_SMEM>>>();
    gru_kernel<<<(NN * 64 + 255) / 256, 256>>>(hx, bi, bh, out);
}

// round 16
// speedup vs baseline: 1.5497x; 1.5497x over previous
#include <cuda_runtime.h>
#include <cuda_fp16.h>
#include <cstdint>

#define NN 50000
#define NE 800000
#define DIM 128
#define NO 384   /* 3*HIDDEN */
#define NBLK 49  /* scan blocks of 1024: 49*1024 = 50176 >= NN */

// ---------------- scratch (device globals: allocation-free) ----------------
// g_degout/g_degin zero at load (.bss), re-zeroed at END of each launch (gru_kernel).
__device__ __half g_fh16[(size_t)NN * 256];  // [node][0:128)=nsrc*feat, [128:256)=nsrc*hx
__device__ __half g_a16f[(size_t)NN * DIM];  // fp16 A matrices (ndst folded)
__device__ __half g_a16h[(size_t)NN * DIM];
__device__ __half g_C1[(size_t)NN * NO];     // fp16 intermediates
__device__ __half g_C2[(size_t)NN * NO];
__device__ __half g_Bih[NO * DIM];   // Wi^T fp16  [n][k]
__device__ __half g_Bhh[NO * DIM];   // Wh^T fp16
__device__ float g_nsrc[NN];
__device__ float g_ndst[NN];
__device__ int   g_degout[NN];
__device__ int   g_degin[NN];
__device__ int   g_off[NN];          // block-local exclusive offsets
__device__ int   g_cur[NN];          // block-local cursors for csr
__device__ int   g_bsum[NBLK];
__device__ int   g_boff[NBLK];       // block base offsets
__device__ int   g_csrc[NE];

__device__ __forceinline__ uint32_t smem_u32(const void* p) {
    uint32_t a;
    asm("{ .reg .u64 t; cvta.to.shared.u64 t, %1; cvt.u32.u64 %0, t; }" : "=r"(a) : "l"(p));
    return a;
}

// ---------------- kernel 1: degrees (counters pre-zeroed by previous launch) ------
__global__ void deg_kernel(const int* __restrict__ src, const int* __restrict__ dst) {
    int e = blockIdx.x * blockDim.x + threadIdx.x;
    if (e < NE) {
        atomicAdd(&g_degout[src[e]], 1);
        atomicAdd(&g_degin[dst[e]], 1);
    }
}

// ---------------- kernel 2: block-local scan + norms (coalesced, parallel) --------
__global__ __launch_bounds__(1024) void scan1_kernel() {
    __shared__ int sm[1024];
    int t = threadIdx.x;
    int idx = blockIdx.x * 1024 + t;
    int d = (idx < NN) ? g_degin[idx] : 0;
    sm[t] = d;
    __syncthreads();
    for (int s = 1; s < 1024; s <<= 1) {
        int v = (t >= s) ? sm[t - s] : 0;
        __syncthreads();
        sm[t] += v;
        __syncthreads();
    }
    int excl = (t == 0) ? 0 : sm[t - 1];
    if (idx < NN) {
        g_off[idx] = excl;
        g_cur[idx] = excl;
        g_nsrc[idx] = rsqrtf(fmaxf((float)g_degout[idx], 1.f));
        g_ndst[idx] = rsqrtf(fmaxf((float)d, 1.f));
    }
    if (t == 1023) g_bsum[blockIdx.x] = sm[1023];
}

// ---------------- kernel 3: scan of 49 block sums (tiny) ----------------
__global__ void scan2_kernel() {
    if (threadIdx.x == 0) {
        int run = 0;
        for (int b = 0; b < NBLK; b++) {
            g_boff[b] = run;
            run += g_bsum[b];
        }
    }
}

// ---------------- kernel 4: merged mid stage (conv + csr + prepw) -----------------
__global__ __launch_bounds__(256) void mid_kernel(
    const float* __restrict__ feat, const float* __restrict__ hx,
    const float* __restrict__ Wi, const float* __restrict__ Wh,
    const int* __restrict__ src, const int* __restrict__ dst)
{
    int i = blockIdx.x * blockDim.x + threadIdx.x;

    // --- conv: feat/hx -> interleaved fp16 with nsrc pre-folded ---
    if (i < NN * DIM / 4) {
        int n = i >> 5, q = i & 31;
        float ns = g_nsrc[n];
        float4 f = reinterpret_cast<const float4*>(feat)[i];
        float4 h = reinterpret_cast<const float4*>(hx)[i];
        __half2 f01 = __float22half2_rn(make_float2(ns * f.x, ns * f.y));
        __half2 f23 = __float22half2_rn(make_float2(ns * f.z, ns * f.w));
        __half2 h01 = __float22half2_rn(make_float2(ns * h.x, ns * h.y));
        __half2 h23 = __float22half2_rn(make_float2(ns * h.z, ns * h.w));
        uint2* fh = reinterpret_cast<uint2*>(g_fh16);
        fh[n * 64 + q] =
            make_uint2(*reinterpret_cast<uint32_t*>(&f01), *reinterpret_cast<uint32_t*>(&f23));
        fh[n * 64 + 32 + q] =
            make_uint2(*reinterpret_cast<uint32_t*>(&h01), *reinterpret_cast<uint32_t*>(&h23));
    }

    // --- csr: bin edges by dst (global pos = local cursor + block base) ---
    if (i < NE) {
        int d = dst[i];
        int pos = atomicAdd(&g_cur[d], 1) + __ldg(g_boff + (d >> 10));
        g_csrc[pos] = src[i];
    }

    // --- prepw: W^T -> fp16 ---
    if (i < NO * DIM) {
        int n = i >> 7, k = i & 127;
        g_Bih[i] = __float2half(Wi[k * NO + n]);
        g_Bhh[i] = __float2half(Wh[k * NO + n]);
    }
}

// ---------------- kernel 5: aggregation (warp per dst, 1 LDG.128/edge) ------------
__device__ __forceinline__ void acc8(uint4 v, float4& a0, float4& a1) {
    float2 x = __half22float2(*reinterpret_cast<__half2*>(&v.x));
    float2 y = __half22float2(*reinterpret_cast<__half2*>(&v.y));
    float2 z = __half22float2(*reinterpret_cast<__half2*>(&v.z));
    float2 w = __half22float2(*reinterpret_cast<__half2*>(&v.w));
    a0.x += x.x; a0.y += x.y; a0.z += y.x; a0.w += y.y;
    a1.x += z.x; a1.y += z.y; a1.z += w.x; a1.w += w.y;
}

__global__ __launch_bounds__(256) void agg_kernel() {
    int w = (blockIdx.x * blockDim.x + threadIdx.x) >> 5;
    int lane = threadIdx.x & 31;
    if (w >= NN) return;
    int beg = g_off[w] + __ldg(g_boff + (w >> 10));
    int end = beg + g_degin[w];
    const uint4* fh = reinterpret_cast<const uint4*>(g_fh16);
    float4 a0 = make_float4(0.f, 0.f, 0.f, 0.f);
    float4 a1 = make_float4(0.f, 0.f, 0.f, 0.f);
    int p = beg;
    for (; p + 7 < end; p += 8) {
        int s[8];
        uint4 v[8];
#pragma unroll
        for (int j = 0; j < 8; j++) s[j] = __ldg(g_csrc + p + j);
#pragma unroll
        for (int j = 0; j < 8; j++) v[j] = fh[s[j] * 32 + lane];
#pragma unroll
        for (int j = 0; j < 8; j++) acc8(v[j], a0, a1);
    }
    for (; p < end; p++) {
        int s = __ldg(g_csrc + p);
        uint4 v = fh[s * 32 + lane];
        acc8(v, a0, a1);
    }
    float nd = g_ndst[w];
    a0.x *= nd; a0.y *= nd; a0.z *= nd; a0.w *= nd;
    a1.x *= nd; a1.y *= nd; a1.z *= nd; a1.w *= nd;
    __half2 o0 = __float22half2_rn(make_float2(a0.x, a0.y));
    __half2 o1 = __float22half2_rn(make_float2(a0.z, a0.w));
    __half2 o2 = __float22half2_rn(make_float2(a1.x, a1.y));
    __half2 o3 = __float22half2_rn(make_float2(a1.z, a1.w));
    uint4 o = make_uint4(*reinterpret_cast<uint32_t*>(&o0), *reinterpret_cast<uint32_t*>(&o1),
                         *reinterpret_cast<uint32_t*>(&o2), *reinterpret_cast<uint32_t*>(&o3));
    if (lane < 16) reinterpret_cast<uint4*>(g_a16f)[w * 16 + lane] = o;
    else           reinterpret_cast<uint4*>(g_a16h)[w * 16 + lane - 16] = o;
}

// ---------------- kernel 6: mma.sync fp16 GEMM, both operands cp.async ------------
// CTA tile 128(M) x 128(N), occupancy 3, warp tile 64x32 (2x4 warps).
#define PITCH 136                         /* fp16 per smem row (272B) */
#define S_A  0
#define S_B  (128 * PITCH * 2)            /* 34816 */
#define GEMM_SMEM (S_B + 128 * PITCH * 2) /* 69632; x3 CTAs <= 227KB */

__global__ __launch_bounds__(256, 3) void gemm_kernel() {
    extern __shared__ char smem[];
    uint32_t sb = smem_u32(smem);
    int tid = threadIdx.x, lane = tid & 31, wid = tid >> 5;
    int warp_m = wid & 1, warp_n = wid >> 1;   // 2 x 4 warps, warp tile 64 x 32
    int m0 = blockIdx.x * 128, n0 = blockIdx.y * 128;
    const __half* A      = blockIdx.z ? g_a16h : g_a16f;
    const __half* B      = blockIdx.z ? g_Bhh  : g_Bih;
    __half* C            = blockIdx.z ? g_C2   : g_C1;

    // ---- A and B tiles via cp.async (128 rows x 16 uint4 each) ----
    {
        const uint4* AU = reinterpret_cast<const uint4*>(A);
        const uint4* BU = reinterpret_cast<const uint4*>(B);
#pragma unroll
        for (int i = 0; i < 8; i++) {
            int p = tid + i * 256;               // 2048 per tile
            int r = p >> 4, q = p & 15;
            uint32_t doff = (uint32_t)(r * PITCH * 2 + q * 16);
            int gm = m0 + r;
            if (gm < NN) {
                const uint4* ga = AU + gm * 16 + q;
                asm volatile("cp.async.cg.shared.global [%0], [%1], 16;"
                             :: "r"(sb + S_A + doff), "l"(ga) : "memory");
            } else {
                *reinterpret_cast<uint4*>(smem + S_A + doff) = make_uint4(0u, 0u, 0u, 0u);
            }
            const uint4* gb = BU + (n0 + r) * 16 + q;
            asm volatile("cp.async.cg.shared.global [%0], [%1], 16;"
                         :: "r"(sb + S_B + doff), "l"(gb) : "memory");
        }
        asm volatile("cp.async.commit_group;" ::: "memory");
        asm volatile("cp.async.wait_group 0;" ::: "memory");
    }
    __syncthreads();

    float acc[4][4][4];
#pragma unroll
    for (int mi = 0; mi < 4; mi++)
#pragma unroll
        for (int ni = 0; ni < 4; ni++)
#pragma unroll
            for (int j = 0; j < 4; j++) acc[mi][ni][j] = 0.f;

    int a_row = (lane & 7) + ((lane >> 3) & 1) * 8;
    int a_kof = (lane >> 4) * 8;
    int b_row = (lane & 7) + (lane >> 4) * 8;
    int b_kof = ((lane >> 3) & 1) * 8;

    uint32_t sA = sb + S_A;
    uint32_t sB = sb + S_B;
#pragma unroll
    for (int ks = 0; ks < 8; ks++) {
        int k0 = ks * 16;
        uint32_t a[4][4], b[4][2];
#pragma unroll
        for (int mi = 0; mi < 4; mi++) {
            uint32_t addr = sA + ((warp_m * 64 + mi * 16 + a_row) * PITCH + k0 + a_kof) * 2;
            asm volatile("ldmatrix.sync.aligned.m8n8.x4.shared.b16 {%0,%1,%2,%3}, [%4];"
                         : "=r"(a[mi][0]), "=r"(a[mi][1]), "=r"(a[mi][2]), "=r"(a[mi][3])
                         : "r"(addr));
        }
#pragma unroll
        for (int nh = 0; nh < 2; nh++) {
            uint32_t addr = sB + ((warp_n * 32 + nh * 16 + b_row) * PITCH + k0 + b_kof) * 2;
            uint32_t r0, r1, r2, r3;
            asm volatile("ldmatrix.sync.aligned.m8n8.x4.shared.b16 {%0,%1,%2,%3}, [%4];"
                         : "=r"(r0), "=r"(r1), "=r"(r2), "=r"(r3)
                         : "r"(addr));
            b[nh * 2][0] = r0; b[nh * 2][1] = r1;
            b[nh * 2 + 1][0] = r2; b[nh * 2 + 1][1] = r3;
        }
#pragma unroll
        for (int mi = 0; mi < 4; mi++)
#pragma unroll
            for (int ni = 0; ni < 4; ni++) {
                asm volatile(
                    "mma.sync.aligned.m16n8k16.row.col.f32.f16.f16.f32 "
                    "{%0,%1,%2,%3}, {%4,%5,%6,%7}, {%8,%9}, {%0,%1,%2,%3};"
                    : "+f"(acc[mi][ni][0]), "+f"(acc[mi][ni][1]),
                      "+f"(acc[mi][ni][2]), "+f"(acc[mi][ni][3])
                    : "r"(a[mi][0]), "r"(a[mi][1]), "r"(a[mi][2]), "r"(a[mi][3]),
                      "r"(b[ni][0]), "r"(b[ni][1]));
            }
    }

    // ---- epilogue: fp16 stores ----
#pragma unroll
    for (int mi = 0; mi < 4; mi++) {
        int row = m0 + warp_m * 64 + mi * 16 + (lane >> 2);
#pragma unroll
        for (int ni = 0; ni < 4; ni++) {
            int col = n0 + warp_n * 32 + ni * 8 + (lane & 3) * 2;
            if (row < NN) {
                *reinterpret_cast<__half2*>(C + (size_t)row * NO + col) =
                    __float22half2_rn(make_float2(acc[mi][ni][0], acc[mi][ni][1]));
            }
            if (row + 8 < NN) {
                *reinterpret_cast<__half2*>(C + (size_t)(row + 8) * NO + col) =
                    __float22half2_rn(make_float2(acc[mi][ni][2], acc[mi][ni][3]));
            }
        }
    }
}

// ---------------- kernel 7: GRU gating + counter re-zero for next launch ----------
__global__ __launch_bounds__(256) void gru_kernel(
    const float* __restrict__ hx, const float* __restrict__ bi,
    const float* __restrict__ bh, float* __restrict__ out)
{
    int idx = blockIdx.x * blockDim.x + threadIdx.x;   // NN * 64 threads
    if (idx < NN) { g_degout[idx] = 0; g_degin[idx] = 0; }   // prep next launch
    if (idx >= NN * 64) return;
    int n = idx >> 6, ch = (idx & 63);
    const __half2* c1 = reinterpret_cast<const __half2*>(g_C1 + (size_t)n * NO);
    const __half2* c2 = reinterpret_cast<const __half2*>(g_C2 + (size_t)n * NO);
    int c = ch * 2;
    float2 c1r = __half22float2(c1[ch]);
    float2 c1z = __half22float2(c1[ch + 64]);
    float2 c1n = __half22float2(c1[ch + 128]);
    float2 c2r = __half22float2(c2[ch]);
    float2 c2z = __half22float2(c2[ch + 64]);
    float2 c2n = __half22float2(c2[ch + 128]);
    float2 bir = *reinterpret_cast<const float2*>(bi + c);
    float2 biz = *reinterpret_cast<const float2*>(bi + c + 128);
    float2 bin = *reinterpret_cast<const float2*>(bi + c + 256);
    float2 bhr = *reinterpret_cast<const float2*>(bh + c);
    float2 bhz = *reinterpret_cast<const float2*>(bh + c + 128);
    float2 bhn = *reinterpret_cast<const float2*>(bh + c + 256);
    float2 hv = *reinterpret_cast<const float2*>(hx + (size_t)n * DIM + c);
    float2 o;
    {
        float r = 1.f / (1.f + __expf(-(c1r.x + c2r.x + bir.x + bhr.x)));
        float z = 1.f / (1.f + __expf(-(c1z.x + c2z.x + biz.x + bhz.x)));
        float nn = tanhf(c1n.x + bin.x + r * (c2n.x + bhn.x));
        o.x = (1.f - z) * nn + z * hv.x;
    }
    {
        float r = 1.f / (1.f + __expf(-(c1r.y + c2r.y + bir.y + bhr.y)));
        float z = 1.f / (1.f + __expf(-(c1z.y + c2z.y + biz.y + bhz.y)));
        float nn = tanhf(c1n.y + bin.y + r * (c2n.y + bhn.y));
        o.y = (1.f - z) * nn + z * hv.y;
    }
    *reinterpret_cast<float2*>(out + (size_t)n * DIM + c) = o;
}

// ---------------- launch ----------------
extern "C" void kernel_launch(void* const* d_in, const int* in_sizes, int n_in,
                              void* d_out, int out_size)
{
    const float* feat = (const float*)d_in[0];
    const float* hx   = (const float*)d_in[1];
    const float* Wi   = (const float*)d_in[2];
    const float* bi   = (const float*)d_in[3];
    const float* Wh   = (const float*)d_in[4];
    const float* bh   = (const float*)d_in[5];
    const int*   src  = (const int*)d_in[6];
    const int*   dst  = (const int*)d_in[7];
    float* out = (float*)d_out;

    cudaFuncSetAttribute(gemm_kernel, cudaFuncAttributeMaxDynamicSharedMemorySize, GEMM_SMEM);

    deg_kernel<<<(NE + 255) / 256, 256>>>(src, dst);
    scan1_kernel<<<NBLK, 1024>>>();
    scan2_kernel<<<1, 32>>>();
    mid_kernel<<<(NN * DIM / 4 + 255) / 256, 256>>>(feat, hx, Wi, Wh, src, dst);
    agg_kernel<<<(NN * 32 + 255) / 256, 256>>>();
    gemm_kernel<<<dim3((NN + 127) / 128, NO / 128, 2), 256, GEMM_SMEM>>>();
    gru_kernel<<<(NN * 64 + 255) / 256, 256>>>(hx, bi, bh, out);
}

// round 17
// speedup vs baseline: 1.7335x; 1.1186x over previous
#include <cuda_runtime.h>
#include <cuda_fp16.h>
#include <cstdint>

#define NN 50000
#define NE 800000
#define DIM 128
#define NO 384   /* 3*HIDDEN */
#define NBLK 49  /* scan blocks of 1024: 49*1024 = 50176 >= NN */

// ---------------- scratch (device globals: allocation-free) ----------------
// g_degout/g_degin zero at load (.bss), re-zeroed at END of each launch (gru_kernel).
__device__ __half g_fh16[(size_t)NN * 256];  // [node][0:128)=nsrc*feat, [128:256)=nsrc*hx
__device__ __half g_a16f[(size_t)NN * DIM];  // fp16 A matrices (ndst folded)
__device__ __half g_a16h[(size_t)NN * DIM];
__device__ __half g_C1[(size_t)NN * NO];     // fp16 intermediates
__device__ __half g_C2[(size_t)NN * NO];
__device__ __half g_Bih[NO * DIM];   // Wi^T fp16  [n][k]
__device__ __half g_Bhh[NO * DIM];   // Wh^T fp16
__device__ float g_nsrc[NN];
__device__ float g_ndst[NN];
__device__ int   g_degout[NN];
__device__ int   g_degin[NN];
__device__ int   g_off[NN];          // block-local exclusive offsets
__device__ int   g_cur[NN];          // block-local cursors for csr
__device__ int   g_bsum[NBLK];
__device__ int   g_boff[NBLK];       // block base offsets
__device__ int   g_csrc[NE];

__device__ __forceinline__ uint32_t smem_u32(const void* p) {
    uint32_t a;
    asm("{ .reg .u64 t; cvta.to.shared.u64 t, %1; cvt.u32.u64 %0, t; }" : "=r"(a) : "l"(p));
    return a;
}

// ---------------- kernel 1: degrees (4 edges/thread, int4 loads) ------------------
__global__ void deg_kernel(const int* __restrict__ src, const int* __restrict__ dst) {
    int e4 = blockIdx.x * blockDim.x + threadIdx.x;
    if (e4 < NE / 4) {
        int4 s = __ldg(reinterpret_cast<const int4*>(src) + e4);
        int4 d = __ldg(reinterpret_cast<const int4*>(dst) + e4);
        atomicAdd(&g_degout[s.x], 1);
        atomicAdd(&g_degout[s.y], 1);
        atomicAdd(&g_degout[s.z], 1);
        atomicAdd(&g_degout[s.w], 1);
        atomicAdd(&g_degin[d.x], 1);
        atomicAdd(&g_degin[d.y], 1);
        atomicAdd(&g_degin[d.z], 1);
        atomicAdd(&g_degin[d.w], 1);
    }
}

// ---------------- kernel 2: block-local scan + norms (coalesced, parallel) --------
__global__ __launch_bounds__(1024) void scan1_kernel() {
    __shared__ int sm[1024];
    int t = threadIdx.x;
    int idx = blockIdx.x * 1024 + t;
    int d = (idx < NN) ? g_degin[idx] : 0;
    sm[t] = d;
    __syncthreads();
    for (int s = 1; s < 1024; s <<= 1) {
        int v = (t >= s) ? sm[t - s] : 0;
        __syncthreads();
        sm[t] += v;
        __syncthreads();
    }
    int excl = (t == 0) ? 0 : sm[t - 1];
    if (idx < NN) {
        g_off[idx] = excl;
        g_cur[idx] = excl;
        g_nsrc[idx] = rsqrtf(fmaxf((float)g_degout[idx], 1.f));
        g_ndst[idx] = rsqrtf(fmaxf((float)d, 1.f));
    }
    if (t == 1023) g_bsum[blockIdx.x] = sm[1023];
}

// ---------------- kernel 3: scan of 49 block sums (tiny) ----------------
__global__ void scan2_kernel() {
    if (threadIdx.x == 0) {
        int run = 0;
        for (int b = 0; b < NBLK; b++) {
            g_boff[b] = run;
            run += g_bsum[b];
        }
    }
}

// ---------------- kernel 4: merged mid stage (conv + csr + prepw) -----------------
__global__ __launch_bounds__(256) void mid_kernel(
    const float* __restrict__ feat, const float* __restrict__ hx,
    const float* __restrict__ Wi, const float* __restrict__ Wh,
    const int* __restrict__ src, const int* __restrict__ dst)
{
    int i = blockIdx.x * blockDim.x + threadIdx.x;

    // --- conv: feat/hx -> interleaved fp16 with nsrc pre-folded ---
    if (i < NN * DIM / 4) {
        int n = i >> 5, q = i & 31;
        float ns = g_nsrc[n];
        float4 f = reinterpret_cast<const float4*>(feat)[i];
        float4 h = reinterpret_cast<const float4*>(hx)[i];
        __half2 f01 = __float22half2_rn(make_float2(ns * f.x, ns * f.y));
        __half2 f23 = __float22half2_rn(make_float2(ns * f.z, ns * f.w));
        __half2 h01 = __float22half2_rn(make_float2(ns * h.x, ns * h.y));
        __half2 h23 = __float22half2_rn(make_float2(ns * h.z, ns * h.w));
        uint2* fh = reinterpret_cast<uint2*>(g_fh16);
        fh[n * 64 + q] =
            make_uint2(*reinterpret_cast<uint32_t*>(&f01), *reinterpret_cast<uint32_t*>(&f23));
        fh[n * 64 + 32 + q] =
            make_uint2(*reinterpret_cast<uint32_t*>(&h01), *reinterpret_cast<uint32_t*>(&h23));
    }

    // --- csr: bin edges by dst (global pos = local cursor + block base) ---
    if (i < NE) {
        int d = dst[i];
        int pos = atomicAdd(&g_cur[d], 1) + __ldg(g_boff + (d >> 10));
        g_csrc[pos] = src[i];
    }

    // --- prepw: W^T -> fp16 ---
    if (i < NO * DIM) {
        int n = i >> 7, k = i & 127;
        g_Bih[i] = __float2half(Wi[k * NO + n]);
        g_Bhh[i] = __float2half(Wh[k * NO + n]);
    }
}

// ---------------- kernel 5: aggregation (warp per dst, 1 LDG.128/edge) ------------
__device__ __forceinline__ void acc8(uint4 v, float4& a0, float4& a1) {
    float2 x = __half22float2(*reinterpret_cast<__half2*>(&v.x));
    float2 y = __half22float2(*reinterpret_cast<__half2*>(&v.y));
    float2 z = __half22float2(*reinterpret_cast<__half2*>(&v.z));
    float2 w = __half22float2(*reinterpret_cast<__half2*>(&v.w));
    a0.x += x.x; a0.y += x.y; a0.z += y.x; a0.w += y.y;
    a1.x += z.x; a1.y += z.y; a1.z += w.x; a1.w += w.y;
}

__global__ __launch_bounds__(256) void agg_kernel() {
    int w = (blockIdx.x * blockDim.x + threadIdx.x) >> 5;
    int lane = threadIdx.x & 31;
    if (w >= NN) return;
    int beg = g_off[w] + __ldg(g_boff + (w >> 10));
    int end = beg + g_degin[w];
    const uint4* fh = reinterpret_cast<const uint4*>(g_fh16);
    float4 a0 = make_float4(0.f, 0.f, 0.f, 0.f);
    float4 a1 = make_float4(0.f, 0.f, 0.f, 0.f);
    int p = beg;
    for (; p + 7 < end; p += 8) {
        int s[8];
        uint4 v[8];
#pragma unroll
        for (int j = 0; j < 8; j++) s[j] = __ldg(g_csrc + p + j);
#pragma unroll
        for (int j = 0; j < 8; j++) v[j] = fh[s[j] * 32 + lane];
#pragma unroll
        for (int j = 0; j < 8; j++) acc8(v[j], a0, a1);
    }
    for (; p < end; p++) {
        int s = __ldg(g_csrc + p);
        uint4 v = fh[s * 32 + lane];
        acc8(v, a0, a1);
    }
    float nd = g_ndst[w];
    a0.x *= nd; a0.y *= nd; a0.z *= nd; a0.w *= nd;
    a1.x *= nd; a1.y *= nd; a1.z *= nd; a1.w *= nd;
    __half2 o0 = __float22half2_rn(make_float2(a0.x, a0.y));
    __half2 o1 = __float22half2_rn(make_float2(a0.z, a0.w));
    __half2 o2 = __float22half2_rn(make_float2(a1.x, a1.y));
    __half2 o3 = __float22half2_rn(make_float2(a1.z, a1.w));
    uint4 o = make_uint4(*reinterpret_cast<uint32_t*>(&o0), *reinterpret_cast<uint32_t*>(&o1),
                         *reinterpret_cast<uint32_t*>(&o2), *reinterpret_cast<uint32_t*>(&o3));
    if (lane < 16) reinterpret_cast<uint4*>(g_a16f)[w * 16 + lane] = o;
    else           reinterpret_cast<uint4*>(g_a16h)[w * 16 + lane - 16] = o;
}

// ---------------- kernel 6: A-resident y-loop GEMM, double-buffered B -------------
// grid (391, 2): each CTA owns 128 M-rows, loops the 3 N-tiles of 128.
// smem: A resident + 2 B buffers. occ 2.
#define PITCH 136                          /* fp16 per smem row (272B) */
#define S_A   0
#define S_B0  (128 * PITCH * 2)            /* 34816 */
#define S_B1  (2 * 128 * PITCH * 2)        /* 69632 */
#define GEMM_SMEM (3 * 128 * PITCH * 2)    /* 104448; x2 CTAs <= 227KB */

__device__ __forceinline__ void load_b_tile(uint32_t sdst, const uint4* BU, int n0, int tid) {
#pragma unroll
    for (int i = 0; i < 8; i++) {
        int p = tid + i * 256;
        int r = p >> 4, q = p & 15;
        uint32_t doff = (uint32_t)(r * PITCH * 2 + q * 16);
        asm volatile("cp.async.cg.shared.global [%0], [%1], 16;"
                     :: "r"(sdst + doff), "l"(BU + (n0 + r) * 16 + q) : "memory");
    }
}

__global__ __launch_bounds__(256, 2) void gemm_kernel() {
    extern __shared__ char smem[];
    uint32_t sb = smem_u32(smem);
    int tid = threadIdx.x, lane = tid & 31, wid = tid >> 5;
    int warp_m = wid & 1, warp_n = wid >> 1;   // 2 x 4 warps, warp tile 64 x 32
    int m0 = blockIdx.x * 128;
    const __half* A      = blockIdx.y ? g_a16h : g_a16f;
    const __half* B      = blockIdx.y ? g_Bhh  : g_Bih;
    __half* C            = blockIdx.y ? g_C2   : g_C1;
    const uint4* AU = reinterpret_cast<const uint4*>(A);
    const uint4* BU = reinterpret_cast<const uint4*>(B);

    // group0: A + B(y=0); group1: B(y=1)
    {
#pragma unroll
        for (int i = 0; i < 8; i++) {
            int p = tid + i * 256;
            int r = p >> 4, q = p & 15;
            uint32_t doff = (uint32_t)(r * PITCH * 2 + q * 16);
            int gm = m0 + r;
            if (gm < NN) {
                asm volatile("cp.async.cg.shared.global [%0], [%1], 16;"
                             :: "r"(sb + S_A + doff), "l"(AU + gm * 16 + q) : "memory");
            } else {
                *reinterpret_cast<uint4*>(smem + S_A + doff) = make_uint4(0u, 0u, 0u, 0u);
            }
        }
        load_b_tile(sb + S_B0, BU, 0, tid);
        asm volatile("cp.async.commit_group;" ::: "memory");
        load_b_tile(sb + S_B1, BU, 128, tid);
        asm volatile("cp.async.commit_group;" ::: "memory");
    }

    int a_row = (lane & 7) + ((lane >> 3) & 1) * 8;
    int a_kof = (lane >> 4) * 8;
    int b_row = (lane & 7) + (lane >> 4) * 8;
    int b_kof = ((lane >> 3) & 1) * 8;
    uint32_t sA = sb + S_A;

#pragma unroll 1
    for (int y = 0; y < 3; y++) {
        if (y < 2) { asm volatile("cp.async.wait_group 1;" ::: "memory"); }
        else       { asm volatile("cp.async.wait_group 0;" ::: "memory"); }
        __syncthreads();
        uint32_t sB = sb + ((y & 1) ? S_B1 : S_B0);

        float acc[4][4][4];
#pragma unroll
        for (int mi = 0; mi < 4; mi++)
#pragma unroll
            for (int ni = 0; ni < 4; ni++)
#pragma unroll
                for (int j = 0; j < 4; j++) acc[mi][ni][j] = 0.f;

#pragma unroll
        for (int ks = 0; ks < 8; ks++) {
            int k0 = ks * 16;
            uint32_t a[4][4], b[4][2];
#pragma unroll
            for (int mi = 0; mi < 4; mi++) {
                uint32_t addr = sA + ((warp_m * 64 + mi * 16 + a_row) * PITCH + k0 + a_kof) * 2;
                asm volatile("ldmatrix.sync.aligned.m8n8.x4.shared.b16 {%0,%1,%2,%3}, [%4];"
                             : "=r"(a[mi][0]), "=r"(a[mi][1]), "=r"(a[mi][2]), "=r"(a[mi][3])
                             : "r"(addr));
            }
#pragma unroll
            for (int nh = 0; nh < 2; nh++) {
                uint32_t addr = sB + ((warp_n * 32 + nh * 16 + b_row) * PITCH + k0 + b_kof) * 2;
                uint32_t r0, r1, r2, r3;
                asm volatile("ldmatrix.sync.aligned.m8n8.x4.shared.b16 {%0,%1,%2,%3}, [%4];"
                             : "=r"(r0), "=r"(r1), "=r"(r2), "=r"(r3)
                             : "r"(addr));
                b[nh * 2][0] = r0; b[nh * 2][1] = r1;
                b[nh * 2 + 1][0] = r2; b[nh * 2 + 1][1] = r3;
            }
#pragma unroll
            for (int mi = 0; mi < 4; mi++)
#pragma unroll
                for (int ni = 0; ni < 4; ni++) {
                    asm volatile(
                        "mma.sync.aligned.m16n8k16.row.col.f32.f16.f16.f32 "
                        "{%0,%1,%2,%3}, {%4,%5,%6,%7}, {%8,%9}, {%0,%1,%2,%3};"
                        : "+f"(acc[mi][ni][0]), "+f"(acc[mi][ni][1]),
                          "+f"(acc[mi][ni][2]), "+f"(acc[mi][ni][3])
                        : "r"(a[mi][0]), "r"(a[mi][1]), "r"(a[mi][2]), "r"(a[mi][3]),
                          "r"(b[ni][0]), "r"(b[ni][1]));
                }
        }

        if (y == 0) {
            __syncthreads();                        // all warps done reading B0
            load_b_tile(sb + S_B0, BU, 256, tid);   // prefetch y=2
            asm volatile("cp.async.commit_group;" ::: "memory");
        }

        // ---- store this y's C columns (fp16) ----
        int colb = y * 128;
#pragma unroll
        for (int mi = 0; mi < 4; mi++) {
            int row = m0 + warp_m * 64 + mi * 16 + (lane >> 2);
#pragma unroll
            for (int ni = 0; ni < 4; ni++) {
                int col = colb + warp_n * 32 + ni * 8 + (lane & 3) * 2;
                if (row < NN) {
                    *reinterpret_cast<__half2*>(C + (size_t)row * NO + col) =
                        __float22half2_rn(make_float2(acc[mi][ni][0], acc[mi][ni][1]));
                }
                if (row + 8 < NN) {
                    *reinterpret_cast<__half2*>(C + (size_t)(row + 8) * NO + col) =
                        __float22half2_rn(make_float2(acc[mi][ni][2], acc[mi][ni][3]));
                }
            }
        }
    }
}

// ---------------- kernel 7: GRU gating + counter re-zero for next launch ----------
__global__ __launch_bounds__(256) void gru_kernel(
    const float* __restrict__ hx, const float* __restrict__ bi,
    const float* __restrict__ bh, float* __restrict__ out)
{
    int idx = blockIdx.x * blockDim.x + threadIdx.x;   // NN * 64 threads
    if (idx < NN) { g_degout[idx] = 0; g_degin[idx] = 0; }   // prep next launch
    if (idx >= NN * 64) return;
    int n = idx >> 6, ch = (idx & 63);
    const __half2* c1 = reinterpret_cast<const __half2*>(g_C1 + (size_t)n * NO);
    const __half2* c2 = reinterpret_cast<const __half2*>(g_C2 + (size_t)n * NO);
    int c = ch * 2;
    float2 c1r = __half22float2(c1[ch]);
    float2 c1z = __half22float2(c1[ch + 64]);
    float2 c1n = __half22float2(c1[ch + 128]);
    float2 c2r = __half22float2(c2[ch]);
    float2 c2z = __half22float2(c2[ch + 64]);
    float2 c2n = __half22float2(c2[ch + 128]);
    float2 bir = *reinterpret_cast<const float2*>(bi + c);
    float2 biz = *reinterpret_cast<const float2*>(bi + c + 128);
    float2 bin = *reinterpret_cast<const float2*>(bi + c + 256);
    float2 bhr = *reinterpret_cast<const float2*>(bh + c);
    float2 bhz = *reinterpret_cast<const float2*>(bh + c + 128);
    float2 bhn = *reinterpret_cast<const float2*>(bh + c + 256);
    float2 hv = *reinterpret_cast<const float2*>(hx + (size_t)n * DIM + c);
    float2 o;
    {
        float r = 1.f / (1.f + __expf(-(c1r.x + c2r.x + bir.x + bhr.x)));
        float z = 1.f / (1.f + __expf(-(c1z.x + c2z.x + biz.x + bhz.x)));
        float nn = tanhf(c1n.x + bin.x + r * (c2n.x + bhn.x));
        o.x = (1.f - z) * nn + z * hv.x;
    }
    {
        float r = 1.f / (1.f + __expf(-(c1r.y + c2r.y + bir.y + bhr.y)));
        float z = 1.f / (1.f + __expf(-(c1z.y + c2z.y + biz.y + bhz.y)));
        float nn = tanhf(c1n.y + bin.y + r * (c2n.y + bhn.y));
        o.y = (1.f - z) * nn + z * hv.y;
    }
    *reinterpret_cast<float2*>(out + (size_t)n * DIM + c) = o;
}

// ---------------- launch ----------------
extern "C" void kernel_launch(void* const* d_in, const int* in_sizes, int n_in,
                              void* d_out, int out_size)
{
    const float* feat = (const float*)d_in[0];
    const float* hx   = (const float*)d_in[1];
    const float* Wi   = (const float*)d_in[2];
    const float* bi   = (const float*)d_in[3];
    const float* Wh   = (const float*)d_in[4];
    const float* bh   = (const float*)d_in[5];
    const int*   src  = (const int*)d_in[6];
    const int*   dst  = (const int*)d_in[7];
    float* out = (float*)d_out;

    cudaFuncSetAttribute(gemm_kernel, cudaFuncAttributeMaxDynamicSharedMemorySize, GEMM_SMEM);

    deg_kernel<<<(NE / 4 + 255) / 256, 256>>>(src, dst);
    scan1_kernel<<<NBLK, 1024>>>();
    scan2_kernel<<<1, 32>>>();
    mid_kernel<<<(NN * DIM / 4 + 255) / 256, 256>>>(feat, hx, Wi, Wh, src, dst);
    agg_kernel<<<(NN * 32 + 255) / 256, 256>>>();
    gemm_kernel<<<dim3((NN + 127) / 128, 2), 256, GEMM_SMEM>>>();
    gru_kernel<<<(NN * 64 + 255) / 256, 256>>>(hx, bi, bh, out);
}